// round 1
// baseline (speedup 1.0000x reference)
#include <cuda_runtime.h>

#define BATCH 4
#define SEQ 2048
#define DM 1024
#define NH 16
#define DEPTH 64
#define MROWS (BATCH * SEQ)  // 8192

// ---------------- scratch (allocation-free rule: __device__ globals) --------
__device__ float g_qh[BATCH * NH * SEQ * DEPTH];
__device__ float g_kh[BATCH * NH * SEQ * DEPTH];
__device__ float g_vh[BATCH * NH * SEQ * DEPTH];
__device__ float g_attn[BATCH * NH * SEQ * DEPTH];

// ---------------------------------------------------------------------------
// SGEMM: C[M,N] = A[M,K] @ W[N,K]^T + bias[N]
// GATHER_A: A is stored head-split (B,H,S,d) -> gather into logical (M,K)
// SPLIT_C : store C head-split (B,H,S,d) instead of row-major (M,N)
// BM=BN=128, BK=8, 256 threads, 8x8 microtile.
// ---------------------------------------------------------------------------
template <int GATHER_A, int SPLIT_C>
__global__ __launch_bounds__(256) void sgemm_bias(
    const float* __restrict__ A, const float* __restrict__ W,
    const float* __restrict__ bias, float* __restrict__ C) {
  constexpr int BM = 128, BN = 128, BK = 8, TM = 8, TN = 8;
  constexpr int K = DM, N = DM;
  __shared__ float As[BK][BM];
  __shared__ float Bs[BK][BN];

  const int tid = threadIdx.x;
  const int brow = blockIdx.y * BM;
  const int bcol = blockIdx.x * BN;

  const int a_row = tid >> 1;        // 0..127
  const int a_k4 = (tid & 1) * 4;    // 0 or 4
  const int trow = (tid >> 4) * TM;  // 0..120
  const int tcol = (tid & 15) * TN;  // 0..120

  float acc[TM][TN];
#pragma unroll
  for (int i = 0; i < TM; i++)
#pragma unroll
    for (int j = 0; j < TN; j++) acc[i][j] = 0.f;

  for (int k0 = 0; k0 < K; k0 += BK) {
    const int m = brow + a_row;
    const int kk = k0 + a_k4;
    float4 av;
    if (GATHER_A) {
      // head-split: A[m][kk] at ((b*NH + h)*SEQ + s)*DEPTH + d
      const int idx = ((m >> 11) * NH + (kk >> 6)) * (SEQ * DEPTH) +
                      (m & (SEQ - 1)) * DEPTH + (kk & (DEPTH - 1));
      av = *(const float4*)(A + idx);
    } else {
      av = *(const float4*)(A + (size_t)m * K + kk);
    }
    const float4 wv = *(const float4*)(W + (size_t)(bcol + a_row) * K + kk);

    As[a_k4 + 0][a_row] = av.x;
    As[a_k4 + 1][a_row] = av.y;
    As[a_k4 + 2][a_row] = av.z;
    As[a_k4 + 3][a_row] = av.w;
    Bs[a_k4 + 0][a_row] = wv.x;
    Bs[a_k4 + 1][a_row] = wv.y;
    Bs[a_k4 + 2][a_row] = wv.z;
    Bs[a_k4 + 3][a_row] = wv.w;
    __syncthreads();

#pragma unroll
    for (int k = 0; k < BK; k++) {
      float ar[TM], br[TN];
      *(float4*)&ar[0] = *(const float4*)&As[k][trow];
      *(float4*)&ar[4] = *(const float4*)&As[k][trow + 4];
      *(float4*)&br[0] = *(const float4*)&Bs[k][tcol];
      *(float4*)&br[4] = *(const float4*)&Bs[k][tcol + 4];
#pragma unroll
      for (int i = 0; i < TM; i++)
#pragma unroll
        for (int j = 0; j < TN; j++) acc[i][j] += ar[i] * br[j];
    }
    __syncthreads();
  }

#pragma unroll
  for (int i = 0; i < TM; i++) {
    const int m = brow + trow + i;
#pragma unroll
    for (int j0 = 0; j0 < TN; j0 += 4) {
      const int n = bcol + tcol + j0;
      float4 o;
      o.x = acc[i][j0 + 0] + bias[n + 0];
      o.y = acc[i][j0 + 1] + bias[n + 1];
      o.z = acc[i][j0 + 2] + bias[n + 2];
      o.w = acc[i][j0 + 3] + bias[n + 3];
      int idx;
      if (SPLIT_C) {
        idx = ((m >> 11) * NH + (n >> 6)) * (SEQ * DEPTH) +
              (m & (SEQ - 1)) * DEPTH + (n & (DEPTH - 1));
      } else {
        idx = m * N + n;
      }
      *(float4*)(C + idx) = o;
    }
  }
}

// ---------------------------------------------------------------------------
// Causal flash attention, fp32. Per block: one (b,h) and one 64-row Q tile.
// 256 threads, each owns a 4x4 microtile of the 64x64 S / O tiles.
// Shared: Qs[d][r], Ks[d][c] (reused as Ps[r][k] after S is computed), Vs[k][c]
// => exactly 48 KB static smem.
// ---------------------------------------------------------------------------
__global__ __launch_bounds__(256) void flash_causal(
    const float* __restrict__ qh, const float* __restrict__ kh,
    const float* __restrict__ vh, float* __restrict__ attn) {
  __shared__ float Qs[DEPTH][64];  // [d][r]
  __shared__ float Ks[DEPTH][64];  // [d][c]; reused as Ps[r][k]
  __shared__ float Vs[64][DEPTH];  // [k][c]

  const int tid = threadIdx.x;
  const int bh = blockIdx.y;  // 0..63
  const int qt = blockIdx.x;  // 0..31

  const float* Qg = qh + ((size_t)bh * SEQ + qt * 64) * DEPTH;
  const float* Kg = kh + (size_t)bh * SEQ * DEPTH;
  const float* Vg = vh + (size_t)bh * SEQ * DEPTH;

  const int lrow = tid >> 2;        // 0..63
  const int dseg = (tid & 3) * 16;  // 0,16,32,48

  // load Q tile transposed: Qs[d][r]
#pragma unroll
  for (int s4 = 0; s4 < 16; s4 += 4) {
    float4 v = *(const float4*)(Qg + lrow * DEPTH + dseg + s4);
    Qs[dseg + s4 + 0][lrow] = v.x;
    Qs[dseg + s4 + 1][lrow] = v.y;
    Qs[dseg + s4 + 2][lrow] = v.z;
    Qs[dseg + s4 + 3][lrow] = v.w;
  }

  const int ty = tid >> 4;   // 0..15
  const int tx = tid & 15;   // 0..15
  const int trow = ty * 4;
  const int tcol = tx * 4;

  float m_i[4], l_i[4], o[4][4];
#pragma unroll
  for (int i = 0; i < 4; i++) {
    m_i[i] = -1e30f;
    l_i[i] = 0.f;
#pragma unroll
    for (int j = 0; j < 4; j++) o[i][j] = 0.f;
  }

  float(*Ps)[64] = Ks;  // alias: P tile overwrites K tile (sync-guarded)

  for (int kt = 0; kt <= qt; kt++) {
    __syncthreads();  // prior iteration's Ps/Vs reads done
    // load K transposed + V direct
    const float* kg = Kg + ((size_t)kt * 64 + lrow) * DEPTH + dseg;
    const float* vg = Vg + ((size_t)kt * 64 + lrow) * DEPTH + dseg;
#pragma unroll
    for (int s4 = 0; s4 < 16; s4 += 4) {
      float4 kv4 = *(const float4*)(kg + s4);
      Ks[dseg + s4 + 0][lrow] = kv4.x;
      Ks[dseg + s4 + 1][lrow] = kv4.y;
      Ks[dseg + s4 + 2][lrow] = kv4.z;
      Ks[dseg + s4 + 3][lrow] = kv4.w;
      *(float4*)&Vs[lrow][dseg + s4] = *(const float4*)(vg + s4);
    }
    __syncthreads();

    // S = Q K^T * scale (+ causal mask on diagonal tile)
    float s[4][4];
#pragma unroll
    for (int i = 0; i < 4; i++)
#pragma unroll
      for (int j = 0; j < 4; j++) s[i][j] = 0.f;
#pragma unroll
    for (int d = 0; d < DEPTH; d++) {
      float4 a = *(const float4*)&Qs[d][trow];
      float4 b = *(const float4*)&Ks[d][tcol];
      const float ar[4] = {a.x, a.y, a.z, a.w};
      const float br[4] = {b.x, b.y, b.z, b.w};
#pragma unroll
      for (int i = 0; i < 4; i++)
#pragma unroll
        for (int j = 0; j < 4; j++) s[i][j] += ar[i] * br[j];
    }
    const float scale = 0.125f;
#pragma unroll
    for (int i = 0; i < 4; i++)
#pragma unroll
      for (int j = 0; j < 4; j++) {
        s[i][j] *= scale;
        if (kt == qt && (tcol + j) > (trow + i)) s[i][j] = -1e9f;
      }

    // online softmax
    float alpha[4];
#pragma unroll
    for (int i = 0; i < 4; i++) {
      float mx = fmaxf(fmaxf(s[i][0], s[i][1]), fmaxf(s[i][2], s[i][3]));
      mx = fmaxf(mx, __shfl_xor_sync(0xffffffffu, mx, 1));
      mx = fmaxf(mx, __shfl_xor_sync(0xffffffffu, mx, 2));
      mx = fmaxf(mx, __shfl_xor_sync(0xffffffffu, mx, 4));
      mx = fmaxf(mx, __shfl_xor_sync(0xffffffffu, mx, 8));
      const float mn = fmaxf(m_i[i], mx);
      alpha[i] = __expf(m_i[i] - mn);
      m_i[i] = mn;
      float rs = 0.f;
#pragma unroll
      for (int j = 0; j < 4; j++) {
        s[i][j] = __expf(s[i][j] - mn);
        rs += s[i][j];
      }
      rs += __shfl_xor_sync(0xffffffffu, rs, 1);
      rs += __shfl_xor_sync(0xffffffffu, rs, 2);
      rs += __shfl_xor_sync(0xffffffffu, rs, 4);
      rs += __shfl_xor_sync(0xffffffffu, rs, 8);
      l_i[i] = l_i[i] * alpha[i] + rs;
#pragma unroll
      for (int j = 0; j < 4; j++) o[i][j] *= alpha[i];
    }

    __syncthreads();  // all Ks reads complete before overwriting with P
#pragma unroll
    for (int i = 0; i < 4; i++) {
      float4 p = make_float4(s[i][0], s[i][1], s[i][2], s[i][3]);
      *(float4*)&Ps[trow + i][tcol] = p;
    }
    __syncthreads();

    // O += P @ V
#pragma unroll
    for (int k = 0; k < 64; k++) {
      float4 b = *(const float4*)&Vs[k][tcol];
      const float a0 = Ps[trow + 0][k];
      const float a1 = Ps[trow + 1][k];
      const float a2 = Ps[trow + 2][k];
      const float a3 = Ps[trow + 3][k];
      o[0][0] += a0 * b.x; o[0][1] += a0 * b.y; o[0][2] += a0 * b.z; o[0][3] += a0 * b.w;
      o[1][0] += a1 * b.x; o[1][1] += a1 * b.y; o[1][2] += a1 * b.z; o[1][3] += a1 * b.w;
      o[2][0] += a2 * b.x; o[2][1] += a2 * b.y; o[2][2] += a2 * b.z; o[2][3] += a2 * b.w;
      o[3][0] += a3 * b.x; o[3][1] += a3 * b.y; o[3][2] += a3 * b.z; o[3][3] += a3 * b.w;
    }
  }

  // normalize + write (head-split layout)
  float* og = attn + ((size_t)bh * SEQ + qt * 64) * DEPTH;
#pragma unroll
  for (int i = 0; i < 4; i++) {
    const float inv = 1.0f / l_i[i];
    float4 w = make_float4(o[i][0] * inv, o[i][1] * inv, o[i][2] * inv,
                           o[i][3] * inv);
    *(float4*)(og + (trow + i) * DEPTH + tcol) = w;
  }
}

// ---------------------------------------------------------------------------
extern "C" void kernel_launch(void* const* d_in, const int* in_sizes, int n_in,
                              void* d_out, int out_size) {
  const float* q = (const float*)d_in[0];
  const float* k = (const float*)d_in[1];
  const float* v = (const float*)d_in[2];
  const float* wq_w = (const float*)d_in[3];
  const float* wq_b = (const float*)d_in[4];
  const float* wk_w = (const float*)d_in[5];
  const float* wk_b = (const float*)d_in[6];
  const float* wv_w = (const float*)d_in[7];
  const float* wv_b = (const float*)d_in[8];
  const float* dense_w = (const float*)d_in[9];
  const float* dense_b = (const float*)d_in[10];
  float* out = (float*)d_out;

  float *qh, *kh, *vh, *attn;
  cudaGetSymbolAddress((void**)&qh, g_qh);
  cudaGetSymbolAddress((void**)&kh, g_kh);
  cudaGetSymbolAddress((void**)&vh, g_vh);
  cudaGetSymbolAddress((void**)&attn, g_attn);

  dim3 gg(DM / 128, MROWS / 128);  // (8, 64)
  dim3 bb(256);
  sgemm_bias<0, 1><<<gg, bb>>>(q, wq_w, wq_b, qh);
  sgemm_bias<0, 1><<<gg, bb>>>(k, wk_w, wk_b, kh);
  sgemm_bias<0, 1><<<gg, bb>>>(v, wv_w, wv_b, vh);

  dim3 fg(SEQ / 64, BATCH * NH);  // (32, 64)
  flash_causal<<<fg, bb>>>(qh, kh, vh, attn);

  sgemm_bias<1, 0><<<gg, bb>>>(attn, dense_w, dense_b, out);
}

// round 3
// speedup vs baseline: 1.5847x; 1.5847x over previous
#include <cuda_runtime.h>
#include <cuda_bf16.h>
#include <cstdint>

#define BATCH 4
#define SEQ 2048
#define DM 1024
#define NH 16
#define DEPTH 64
#define MROWS (BATCH * SEQ)  // 8192

// ---------------- scratch (allocation-free rule: __device__ globals) --------
__device__ float g_qh[BATCH * NH * SEQ * DEPTH];
__device__ float g_kh[BATCH * NH * SEQ * DEPTH];
__device__ float g_vh[BATCH * NH * SEQ * DEPTH];
__device__ float g_attn[BATCH * NH * SEQ * DEPTH];
__device__ __nv_bfloat16 g_ihi[3][MROWS * DM];
__device__ __nv_bfloat16 g_ilo[3][MROWS * DM];
__device__ __nv_bfloat16 g_whi[4][DM * DM];
__device__ __nv_bfloat16 g_wlo[4][DM * DM];

// ---------------------------- PTX helpers ----------------------------------
__device__ __forceinline__ uint32_t smem_u32(const void* p) {
  uint32_t a;
  asm("{ .reg .u64 t; cvta.to.shared.u64 t, %1; cvt.u32.u64 %0, t; }"
      : "=r"(a) : "l"(p));
  return a;
}
__device__ __forceinline__ void cp_async16(uint32_t dst, const void* src) {
  asm volatile("cp.async.cg.shared.global [%0], [%1], 16;" ::"r"(dst),
               "l"(src));
}
#define CP_COMMIT() asm volatile("cp.async.commit_group;" ::: "memory")
#define CP_WAIT(n) asm volatile("cp.async.wait_group %0;" ::"n"(n) : "memory")

#define MMA16816(d, a, b)                                                   \
  asm volatile(                                                             \
      "mma.sync.aligned.m16n8k16.row.col.f32.bf16.bf16.f32 "                \
      "{%0,%1,%2,%3}, {%4,%5,%6,%7}, {%8,%9}, {%0,%1,%2,%3};"               \
      : "+f"((d)[0]), "+f"((d)[1]), "+f"((d)[2]), "+f"((d)[3])              \
      : "r"((a)[0]), "r"((a)[1]), "r"((a)[2]), "r"((a)[3]), "r"((b)[0]),    \
        "r"((b)[1]))

// ---------------------------------------------------------------------------
// fp32 -> bf16 hi/lo split converters
// ---------------------------------------------------------------------------
__global__ __launch_bounds__(256) void split_rm(const float* __restrict__ x,
                                                __nv_bfloat16* __restrict__ hi,
                                                __nv_bfloat16* __restrict__ lo,
                                                int n4) {
  int i = blockIdx.x * 256 + threadIdx.x;
  if (i >= n4) return;
  float4 v = ((const float4*)x)[i];
  float f[4] = {v.x, v.y, v.z, v.w};
  __nv_bfloat16 h[4], l[4];
#pragma unroll
  for (int j = 0; j < 4; j++) {
    h[j] = __float2bfloat16_rn(f[j]);
    l[j] = __float2bfloat16_rn(f[j] - __bfloat162float(h[j]));
  }
  ((__nv_bfloat162*)hi)[2 * i + 0] = __halves2bfloat162(h[0], h[1]);
  ((__nv_bfloat162*)hi)[2 * i + 1] = __halves2bfloat162(h[2], h[3]);
  ((__nv_bfloat162*)lo)[2 * i + 0] = __halves2bfloat162(l[0], l[1]);
  ((__nv_bfloat162*)lo)[2 * i + 1] = __halves2bfloat162(l[2], l[3]);
}

// gather from head-split (B,H,S,d) layout into row-major (m,k), then split
__global__ __launch_bounds__(256) void split_gather(
    const float* __restrict__ x, __nv_bfloat16* __restrict__ hi,
    __nv_bfloat16* __restrict__ lo) {
  int i = blockIdx.x * 256 + threadIdx.x;  // over MROWS*DM/4
  int m = i >> 8;
  int k4 = (i & 255) * 4;
  int src = ((m >> 11) * NH + (k4 >> 6)) * (SEQ * DEPTH) +
            (m & (SEQ - 1)) * DEPTH + (k4 & (DEPTH - 1));
  float4 v = *(const float4*)(x + src);
  float f[4] = {v.x, v.y, v.z, v.w};
  __nv_bfloat16 h[4], l[4];
#pragma unroll
  for (int j = 0; j < 4; j++) {
    h[j] = __float2bfloat16_rn(f[j]);
    l[j] = __float2bfloat16_rn(f[j] - __bfloat162float(h[j]));
  }
  ((__nv_bfloat162*)hi)[2 * i + 0] = __halves2bfloat162(h[0], h[1]);
  ((__nv_bfloat162*)hi)[2 * i + 1] = __halves2bfloat162(h[2], h[3]);
  ((__nv_bfloat162*)lo)[2 * i + 0] = __halves2bfloat162(l[0], l[1]);
  ((__nv_bfloat162*)lo)[2 * i + 1] = __halves2bfloat162(l[2], l[3]);
}

// ---------------------------------------------------------------------------
// Tensor-core bf16x3 GEMM via mma.sync: C[M,N] = A[M,K] @ W[N,K]^T + bias
// Block tile 128x128, 8 warps (2x4), warp tile 64x32, K-chunk 64,
// cp.async double buffer. Smem rows padded to 72 bf16 (144 B): fragment
// LDS banks = (4g+tg+c) mod 32 -> conflict-free.
// ---------------------------------------------------------------------------
#define BKG 64
#define NITERG (DM / BKG)                 // 16
#define TSTRIDE_B 144                     // bytes per smem row (72 bf16)
#define TILE_BYTES (128 * TSTRIDE_B)      // 18432
#define STAGE_BYTES (4 * TILE_BYTES)      // 73728
#define GEMM_SMEM (2 * STAGE_BYTES)       // 147456

template <int SPLIT_C>
__global__ __launch_bounds__(256, 1) void gemm_mma(
    const __nv_bfloat16* __restrict__ Ahi, const __nv_bfloat16* __restrict__ Alo,
    const __nv_bfloat16* __restrict__ Whi, const __nv_bfloat16* __restrict__ Wlo,
    const float* __restrict__ bias, float* __restrict__ C) {
  extern __shared__ char sm[];
  const int tid = threadIdx.x;
  const int brow = blockIdx.y * 128;
  const int bcol = blockIdx.x * 128;

  const __nv_bfloat16* srcs[4] = {
      Ahi + (size_t)brow * DM, Alo + (size_t)brow * DM,
      Whi + (size_t)bcol * DM, Wlo + (size_t)bcol * DM};

  auto load_stage = [&](int iter, int s) {
    char* base = sm + s * STAGE_BYTES;
    const int k0 = iter * BKG;
#pragma unroll
    for (int t = 0; t < 4; t++) {
      char* tb = base + t * TILE_BYTES;
      const __nv_bfloat16* gsrc = srcs[t] + k0;
      for (int i = tid; i < 1024; i += 256) {
        const int row = i >> 3, c = i & 7;
        cp_async16(smem_u32(tb + row * TSTRIDE_B + c * 16),
                   gsrc + (size_t)row * DM + c * 8);
      }
    }
    CP_COMMIT();
  };

  const int wid = tid >> 5, lane = tid & 31;
  const int g = lane >> 2, tg = lane & 3;
  const int warp_m = (wid & 1) * 64;
  const int warp_n = (wid >> 1) * 32;

  float acc[4][4][4];
#pragma unroll
  for (int mi = 0; mi < 4; mi++)
#pragma unroll
    for (int ni = 0; ni < 4; ni++)
#pragma unroll
      for (int r = 0; r < 4; r++) acc[mi][ni][r] = 0.f;

  load_stage(0, 0);

  for (int it = 0; it < NITERG; it++) {
    if (it + 1 < NITERG) {
      load_stage(it + 1, (it + 1) & 1);
      CP_WAIT(1);
    } else {
      CP_WAIT(0);
    }
    __syncthreads();
    const char* base = sm + (it & 1) * STAGE_BYTES;
    const char* pAhi = base + 0 * TILE_BYTES;
    const char* pAlo = base + 1 * TILE_BYTES;
    const char* pWhi = base + 2 * TILE_BYTES;
    const char* pWlo = base + 3 * TILE_BYTES;

#pragma unroll
    for (int k16 = 0; k16 < 4; k16++) {
      const int kcb = (k16 * 16 + tg * 2) * 2;  // byte offset of k within row
      uint32_t ahi[4][4], alo[4][4], bhi[4][2], blo[4][2];
#pragma unroll
      for (int mi = 0; mi < 4; mi++) {
        const int r0 = (warp_m + mi * 16 + g) * TSTRIDE_B + kcb;
        const int r1 = r0 + 8 * TSTRIDE_B;
        ahi[mi][0] = *(const uint32_t*)(pAhi + r0);
        ahi[mi][1] = *(const uint32_t*)(pAhi + r1);
        ahi[mi][2] = *(const uint32_t*)(pAhi + r0 + 16);
        ahi[mi][3] = *(const uint32_t*)(pAhi + r1 + 16);
        alo[mi][0] = *(const uint32_t*)(pAlo + r0);
        alo[mi][1] = *(const uint32_t*)(pAlo + r1);
        alo[mi][2] = *(const uint32_t*)(pAlo + r0 + 16);
        alo[mi][3] = *(const uint32_t*)(pAlo + r1 + 16);
      }
#pragma unroll
      for (int ni = 0; ni < 4; ni++) {
        const int r = (warp_n + ni * 8 + g) * TSTRIDE_B + kcb;
        bhi[ni][0] = *(const uint32_t*)(pWhi + r);
        bhi[ni][1] = *(const uint32_t*)(pWhi + r + 16);
        blo[ni][0] = *(const uint32_t*)(pWlo + r);
        blo[ni][1] = *(const uint32_t*)(pWlo + r + 16);
      }
#pragma unroll
      for (int mi = 0; mi < 4; mi++)
#pragma unroll
        for (int ni = 0; ni < 4; ni++) {
          MMA16816(acc[mi][ni], ahi[mi], bhi[ni]);
          MMA16816(acc[mi][ni], ahi[mi], blo[ni]);
          MMA16816(acc[mi][ni], alo[mi], bhi[ni]);
        }
    }
    __syncthreads();
  }

  // epilogue: fragment rows g / g+8, cols tg*2, tg*2+1
#pragma unroll
  for (int mi = 0; mi < 4; mi++) {
    const int m0 = brow + warp_m + mi * 16 + g;
    const int m1 = m0 + 8;
#pragma unroll
    for (int ni = 0; ni < 4; ni++) {
      const int n = bcol + warp_n + ni * 8 + tg * 2;
      const float bx = bias[n], by = bias[n + 1];
      float2 v0 = make_float2(acc[mi][ni][0] + bx, acc[mi][ni][1] + by);
      float2 v1 = make_float2(acc[mi][ni][2] + bx, acc[mi][ni][3] + by);
      int i0, i1;
      if (SPLIT_C) {
        const int hb = ((m0 >> 11) * NH + (n >> 6)) * (SEQ * DEPTH);
        i0 = hb + (m0 & (SEQ - 1)) * DEPTH + (n & (DEPTH - 1));
        const int hb1 = ((m1 >> 11) * NH + (n >> 6)) * (SEQ * DEPTH);
        i1 = hb1 + (m1 & (SEQ - 1)) * DEPTH + (n & (DEPTH - 1));
      } else {
        i0 = m0 * DM + n;
        i1 = m1 * DM + n;
      }
      *(float2*)(C + i0) = v0;
      *(float2*)(C + i1) = v1;
    }
  }
}

// ---------------------------------------------------------------------------
// Causal flash attention, fp32 (unchanged)
// ---------------------------------------------------------------------------
__global__ __launch_bounds__(256) void flash_causal(
    const float* __restrict__ qh, const float* __restrict__ kh,
    const float* __restrict__ vh, float* __restrict__ attn) {
  __shared__ float Qs[DEPTH][64];
  __shared__ float Ks[DEPTH][64];
  __shared__ float Vs[64][DEPTH];

  const int tid = threadIdx.x;
  const int bh = blockIdx.y;
  const int qt = blockIdx.x;

  const float* Qg = qh + ((size_t)bh * SEQ + qt * 64) * DEPTH;
  const float* Kg = kh + (size_t)bh * SEQ * DEPTH;
  const float* Vg = vh + (size_t)bh * SEQ * DEPTH;

  const int lrow = tid >> 2;
  const int dseg = (tid & 3) * 16;

#pragma unroll
  for (int s4 = 0; s4 < 16; s4 += 4) {
    float4 v = *(const float4*)(Qg + lrow * DEPTH + dseg + s4);
    Qs[dseg + s4 + 0][lrow] = v.x;
    Qs[dseg + s4 + 1][lrow] = v.y;
    Qs[dseg + s4 + 2][lrow] = v.z;
    Qs[dseg + s4 + 3][lrow] = v.w;
  }

  const int ty = tid >> 4;
  const int tx = tid & 15;
  const int trow = ty * 4;
  const int tcol = tx * 4;

  float m_i[4], l_i[4], o[4][4];
#pragma unroll
  for (int i = 0; i < 4; i++) {
    m_i[i] = -1e30f;
    l_i[i] = 0.f;
#pragma unroll
    for (int j = 0; j < 4; j++) o[i][j] = 0.f;
  }

  float(*Ps)[64] = Ks;

  for (int kt = 0; kt <= qt; kt++) {
    __syncthreads();
    const float* kg = Kg + ((size_t)kt * 64 + lrow) * DEPTH + dseg;
    const float* vg = Vg + ((size_t)kt * 64 + lrow) * DEPTH + dseg;
#pragma unroll
    for (int s4 = 0; s4 < 16; s4 += 4) {
      float4 kv4 = *(const float4*)(kg + s4);
      Ks[dseg + s4 + 0][lrow] = kv4.x;
      Ks[dseg + s4 + 1][lrow] = kv4.y;
      Ks[dseg + s4 + 2][lrow] = kv4.z;
      Ks[dseg + s4 + 3][lrow] = kv4.w;
      *(float4*)&Vs[lrow][dseg + s4] = *(const float4*)(vg + s4);
    }
    __syncthreads();

    float s[4][4];
#pragma unroll
    for (int i = 0; i < 4; i++)
#pragma unroll
      for (int j = 0; j < 4; j++) s[i][j] = 0.f;
#pragma unroll
    for (int d = 0; d < DEPTH; d++) {
      float4 a = *(const float4*)&Qs[d][trow];
      float4 b = *(const float4*)&Ks[d][tcol];
      const float ar[4] = {a.x, a.y, a.z, a.w};
      const float br[4] = {b.x, b.y, b.z, b.w};
#pragma unroll
      for (int i = 0; i < 4; i++)
#pragma unroll
        for (int j = 0; j < 4; j++) s[i][j] += ar[i] * br[j];
    }
    const float scale = 0.125f;
#pragma unroll
    for (int i = 0; i < 4; i++)
#pragma unroll
      for (int j = 0; j < 4; j++) {
        s[i][j] *= scale;
        if (kt == qt && (tcol + j) > (trow + i)) s[i][j] = -1e9f;
      }

    float alpha[4];
#pragma unroll
    for (int i = 0; i < 4; i++) {
      float mx = fmaxf(fmaxf(s[i][0], s[i][1]), fmaxf(s[i][2], s[i][3]));
      mx = fmaxf(mx, __shfl_xor_sync(0xffffffffu, mx, 1));
      mx = fmaxf(mx, __shfl_xor_sync(0xffffffffu, mx, 2));
      mx = fmaxf(mx, __shfl_xor_sync(0xffffffffu, mx, 4));
      mx = fmaxf(mx, __shfl_xor_sync(0xffffffffu, mx, 8));
      const float mn = fmaxf(m_i[i], mx);
      alpha[i] = __expf(m_i[i] - mn);
      m_i[i] = mn;
      float rs = 0.f;
#pragma unroll
      for (int j = 0; j < 4; j++) {
        s[i][j] = __expf(s[i][j] - mn);
        rs += s[i][j];
      }
      rs += __shfl_xor_sync(0xffffffffu, rs, 1);
      rs += __shfl_xor_sync(0xffffffffu, rs, 2);
      rs += __shfl_xor_sync(0xffffffffu, rs, 4);
      rs += __shfl_xor_sync(0xffffffffu, rs, 8);
      l_i[i] = l_i[i] * alpha[i] + rs;
#pragma unroll
      for (int j = 0; j < 4; j++) o[i][j] *= alpha[i];
    }

    __syncthreads();
#pragma unroll
    for (int i = 0; i < 4; i++) {
      float4 p = make_float4(s[i][0], s[i][1], s[i][2], s[i][3]);
      *(float4*)&Ps[trow + i][tcol] = p;
    }
    __syncthreads();

#pragma unroll
    for (int k = 0; k < 64; k++) {
      float4 b = *(const float4*)&Vs[k][tcol];
      const float a0 = Ps[trow + 0][k];
      const float a1 = Ps[trow + 1][k];
      const float a2 = Ps[trow + 2][k];
      const float a3 = Ps[trow + 3][k];
      o[0][0] += a0 * b.x; o[0][1] += a0 * b.y; o[0][2] += a0 * b.z; o[0][3] += a0 * b.w;
      o[1][0] += a1 * b.x; o[1][1] += a1 * b.y; o[1][2] += a1 * b.z; o[1][3] += a1 * b.w;
      o[2][0] += a2 * b.x; o[2][1] += a2 * b.y; o[2][2] += a2 * b.z; o[2][3] += a2 * b.w;
      o[3][0] += a3 * b.x; o[3][1] += a3 * b.y; o[3][2] += a3 * b.z; o[3][3] += a3 * b.w;
    }
  }

  float* og = attn + ((size_t)bh * SEQ + qt * 64) * DEPTH;
#pragma unroll
  for (int i = 0; i < 4; i++) {
    const float inv = 1.0f / l_i[i];
    float4 w = make_float4(o[i][0] * inv, o[i][1] * inv, o[i][2] * inv,
                           o[i][3] * inv);
    *(float4*)(og + (trow + i) * DEPTH + tcol) = w;
  }
}

// ---------------------------------------------------------------------------
extern "C" void kernel_launch(void* const* d_in, const int* in_sizes, int n_in,
                              void* d_out, int out_size) {
  const float* q = (const float*)d_in[0];
  const float* k = (const float*)d_in[1];
  const float* v = (const float*)d_in[2];
  const float* wq_w = (const float*)d_in[3];
  const float* wq_b = (const float*)d_in[4];
  const float* wk_w = (const float*)d_in[5];
  const float* wk_b = (const float*)d_in[6];
  const float* wv_w = (const float*)d_in[7];
  const float* wv_b = (const float*)d_in[8];
  const float* dense_w = (const float*)d_in[9];
  const float* dense_b = (const float*)d_in[10];
  float* out = (float*)d_out;

  float *qh, *kh, *vh, *attn;
  __nv_bfloat16 *ihi, *ilo, *whi, *wlo;
  cudaGetSymbolAddress((void**)&qh, g_qh);
  cudaGetSymbolAddress((void**)&kh, g_kh);
  cudaGetSymbolAddress((void**)&vh, g_vh);
  cudaGetSymbolAddress((void**)&attn, g_attn);
  cudaGetSymbolAddress((void**)&ihi, g_ihi);
  cudaGetSymbolAddress((void**)&ilo, g_ilo);
  cudaGetSymbolAddress((void**)&whi, g_whi);
  cudaGetSymbolAddress((void**)&wlo, g_wlo);

  static int smem_set = 0;
  if (!smem_set) {
    cudaFuncSetAttribute(gemm_mma<0>,
                         cudaFuncAttributeMaxDynamicSharedMemorySize, GEMM_SMEM);
    cudaFuncSetAttribute(gemm_mma<1>,
                         cudaFuncAttributeMaxDynamicSharedMemorySize, GEMM_SMEM);
    smem_set = 1;
  }

  const size_t ISZ = (size_t)MROWS * DM;  // bf16 elems per input buffer
  const size_t WSZ = (size_t)DM * DM;
  const int n4_in = MROWS * DM / 4;
  const int n4_w = DM * DM / 4;
  dim3 gg(DM / 128, MROWS / 128);  // (8, 64)

  // splits
  split_rm<<<n4_in / 256, 256>>>(q, ihi + 0 * ISZ, ilo + 0 * ISZ, n4_in);
  split_rm<<<n4_in / 256, 256>>>(k, ihi + 1 * ISZ, ilo + 1 * ISZ, n4_in);
  split_rm<<<n4_in / 256, 256>>>(v, ihi + 2 * ISZ, ilo + 2 * ISZ, n4_in);
  split_rm<<<n4_w / 256, 256>>>(wq_w, whi + 0 * WSZ, wlo + 0 * WSZ, n4_w);
  split_rm<<<n4_w / 256, 256>>>(wk_w, whi + 1 * WSZ, wlo + 1 * WSZ, n4_w);
  split_rm<<<n4_w / 256, 256>>>(wv_w, whi + 2 * WSZ, wlo + 2 * WSZ, n4_w);
  split_rm<<<n4_w / 256, 256>>>(dense_w, whi + 3 * WSZ, wlo + 3 * WSZ, n4_w);

  // projections (store head-split)
  gemm_mma<1><<<gg, 256, GEMM_SMEM>>>(ihi + 0 * ISZ, ilo + 0 * ISZ,
                                      whi + 0 * WSZ, wlo + 0 * WSZ, wq_b, qh);
  gemm_mma<1><<<gg, 256, GEMM_SMEM>>>(ihi + 1 * ISZ, ilo + 1 * ISZ,
                                      whi + 1 * WSZ, wlo + 1 * WSZ, wk_b, kh);
  gemm_mma<1><<<gg, 256, GEMM_SMEM>>>(ihi + 2 * ISZ, ilo + 2 * ISZ,
                                      whi + 2 * WSZ, wlo + 2 * WSZ, wv_b, vh);

  // attention
  dim3 fg(SEQ / 64, BATCH * NH);
  flash_causal<<<fg, 256>>>(qh, kh, vh, attn);

  // output projection
  split_gather<<<n4_in / 256, 256>>>(attn, ihi + 0 * ISZ, ilo + 0 * ISZ);
  gemm_mma<0><<<gg, 256, GEMM_SMEM>>>(ihi + 0 * ISZ, ilo + 0 * ISZ,
                                      whi + 3 * WSZ, wlo + 3 * WSZ, dense_b,
                                      out);
}

// round 4
// speedup vs baseline: 2.7001x; 1.7038x over previous
#include <cuda_runtime.h>
#include <cuda_bf16.h>
#include <cstdint>

#define BATCH 4
#define SEQ 2048
#define DM 1024
#define NH 16
#define DEPTH 64
#define MROWS (BATCH * SEQ)  // 8192

typedef __nv_bfloat16 bf16;

// ---------------- scratch (allocation-free rule: __device__ globals) --------
__device__ bf16 g_ihi[3][MROWS * DM];
__device__ bf16 g_ilo[3][MROWS * DM];
__device__ bf16 g_whi[4][DM * DM];
__device__ bf16 g_wlo[4][DM * DM];
__device__ bf16 g_qhi[MROWS * DM], g_qlo[MROWS * DM];
__device__ bf16 g_khi[MROWS * DM], g_klo[MROWS * DM];
__device__ bf16 g_vthi[MROWS * DM], g_vtlo[MROWS * DM];
__device__ bf16 g_ohi[MROWS * DM], g_olo[MROWS * DM];

// ---------------------------- PTX helpers ----------------------------------
__device__ __forceinline__ uint32_t smem_u32(const void* p) {
  uint32_t a;
  asm("{ .reg .u64 t; cvta.to.shared.u64 t, %1; cvt.u32.u64 %0, t; }"
      : "=r"(a) : "l"(p));
  return a;
}
__device__ __forceinline__ void cp_async16(uint32_t dst, const void* src) {
  asm volatile("cp.async.cg.shared.global [%0], [%1], 16;" ::"r"(dst),
               "l"(src));
}
#define CP_COMMIT() asm volatile("cp.async.commit_group;" ::: "memory")
#define CP_WAIT(n) asm volatile("cp.async.wait_group %0;" ::"n"(n) : "memory")

#define MMA16816(d, a, b)                                                   \
  asm volatile(                                                             \
      "mma.sync.aligned.m16n8k16.row.col.f32.bf16.bf16.f32 "                \
      "{%0,%1,%2,%3}, {%4,%5,%6,%7}, {%8,%9}, {%0,%1,%2,%3};"               \
      : "+f"((d)[0]), "+f"((d)[1]), "+f"((d)[2]), "+f"((d)[3])              \
      : "r"((a)[0]), "r"((a)[1]), "r"((a)[2]), "r"((a)[3]), "r"((b)[0]),    \
        "r"((b)[1]))

// pack two floats into bf16x2 hi and lo (split-precision) words
__device__ __forceinline__ void split_pack2(float a, float b, uint32_t& hi,
                                            uint32_t& lo) {
  bf16 ha = __float2bfloat16_rn(a), hb = __float2bfloat16_rn(b);
  bf16 la = __float2bfloat16_rn(a - __bfloat162float(ha));
  bf16 lb = __float2bfloat16_rn(b - __bfloat162float(hb));
  __nv_bfloat162 h2 = __halves2bfloat162(ha, hb);
  __nv_bfloat162 l2 = __halves2bfloat162(la, lb);
  hi = *reinterpret_cast<uint32_t*>(&h2);
  lo = *reinterpret_cast<uint32_t*>(&l2);
}

// ---------------------------------------------------------------------------
// fp32 -> bf16 hi/lo split converter (row-major)
// ---------------------------------------------------------------------------
__global__ __launch_bounds__(256) void split_rm(const float* __restrict__ x,
                                                bf16* __restrict__ hi,
                                                bf16* __restrict__ lo,
                                                int n4) {
  int i = blockIdx.x * 256 + threadIdx.x;
  if (i >= n4) return;
  float4 v = ((const float4*)x)[i];
  uint32_t h0, l0, h1, l1;
  split_pack2(v.x, v.y, h0, l0);
  split_pack2(v.z, v.w, h1, l1);
  ((uint32_t*)hi)[2 * i + 0] = h0;
  ((uint32_t*)hi)[2 * i + 1] = h1;
  ((uint32_t*)lo)[2 * i + 0] = l0;
  ((uint32_t*)lo)[2 * i + 1] = l1;
}

// ---------------------------------------------------------------------------
// Tensor-core bf16x3 GEMM: C = A @ W^T + bias.
// MODE 0: C fp32 row-major.  MODE 1: C bf16 hi/lo, head-split (B,H,S,d).
// MODE 2: C bf16 hi/lo, transposed head-split (B,H,d,S)   [for V]
// ---------------------------------------------------------------------------
#define BKG 64
#define NITERG (DM / BKG)                 // 16
#define TSTRIDE_B 144                     // bytes per smem row (72 bf16)
#define TILE_BYTES (128 * TSTRIDE_B)      // 18432
#define STAGE_BYTES (4 * TILE_BYTES)      // 73728
#define GEMM_SMEM (2 * STAGE_BYTES)       // 147456

template <int MODE>
__global__ __launch_bounds__(256, 1) void gemm_mma(
    const bf16* __restrict__ Ahi, const bf16* __restrict__ Alo,
    const bf16* __restrict__ Whi, const bf16* __restrict__ Wlo,
    const float* __restrict__ bias, float* __restrict__ Cf,
    bf16* __restrict__ Chi, bf16* __restrict__ Clo) {
  extern __shared__ char sm[];
  const int tid = threadIdx.x;
  const int brow = blockIdx.y * 128;
  const int bcol = blockIdx.x * 128;

  const bf16* srcs[4] = {Ahi + (size_t)brow * DM, Alo + (size_t)brow * DM,
                         Whi + (size_t)bcol * DM, Wlo + (size_t)bcol * DM};

  auto load_stage = [&](int iter, int s) {
    char* base = sm + s * STAGE_BYTES;
    const int k0 = iter * BKG;
#pragma unroll
    for (int t = 0; t < 4; t++) {
      char* tb = base + t * TILE_BYTES;
      const bf16* gsrc = srcs[t] + k0;
      for (int i = tid; i < 1024; i += 256) {
        const int row = i >> 3, c = i & 7;
        cp_async16(smem_u32(tb + row * TSTRIDE_B + c * 16),
                   gsrc + (size_t)row * DM + c * 8);
      }
    }
    CP_COMMIT();
  };

  const int wid = tid >> 5, lane = tid & 31;
  const int g = lane >> 2, tg = lane & 3;
  const int warp_m = (wid & 1) * 64;
  const int warp_n = (wid >> 1) * 32;

  float acc[4][4][4];
#pragma unroll
  for (int mi = 0; mi < 4; mi++)
#pragma unroll
    for (int ni = 0; ni < 4; ni++)
#pragma unroll
      for (int r = 0; r < 4; r++) acc[mi][ni][r] = 0.f;

  load_stage(0, 0);

  for (int it = 0; it < NITERG; it++) {
    if (it + 1 < NITERG) {
      load_stage(it + 1, (it + 1) & 1);
      CP_WAIT(1);
    } else {
      CP_WAIT(0);
    }
    __syncthreads();
    const char* base = sm + (it & 1) * STAGE_BYTES;
    const char* pAhi = base + 0 * TILE_BYTES;
    const char* pAlo = base + 1 * TILE_BYTES;
    const char* pWhi = base + 2 * TILE_BYTES;
    const char* pWlo = base + 3 * TILE_BYTES;

#pragma unroll
    for (int k16 = 0; k16 < 4; k16++) {
      const int kcb = (k16 * 16 + tg * 2) * 2;
      uint32_t ahi[4][4], alo[4][4], bhi[4][2], blo[4][2];
#pragma unroll
      for (int mi = 0; mi < 4; mi++) {
        const int r0 = (warp_m + mi * 16 + g) * TSTRIDE_B + kcb;
        const int r1 = r0 + 8 * TSTRIDE_B;
        ahi[mi][0] = *(const uint32_t*)(pAhi + r0);
        ahi[mi][1] = *(const uint32_t*)(pAhi + r1);
        ahi[mi][2] = *(const uint32_t*)(pAhi + r0 + 16);
        ahi[mi][3] = *(const uint32_t*)(pAhi + r1 + 16);
        alo[mi][0] = *(const uint32_t*)(pAlo + r0);
        alo[mi][1] = *(const uint32_t*)(pAlo + r1);
        alo[mi][2] = *(const uint32_t*)(pAlo + r0 + 16);
        alo[mi][3] = *(const uint32_t*)(pAlo + r1 + 16);
      }
#pragma unroll
      for (int ni = 0; ni < 4; ni++) {
        const int r = (warp_n + ni * 8 + g) * TSTRIDE_B + kcb;
        bhi[ni][0] = *(const uint32_t*)(pWhi + r);
        bhi[ni][1] = *(const uint32_t*)(pWhi + r + 16);
        blo[ni][0] = *(const uint32_t*)(pWlo + r);
        blo[ni][1] = *(const uint32_t*)(pWlo + r + 16);
      }
#pragma unroll
      for (int mi = 0; mi < 4; mi++)
#pragma unroll
        for (int ni = 0; ni < 4; ni++) {
          MMA16816(acc[mi][ni], ahi[mi], bhi[ni]);
          MMA16816(acc[mi][ni], ahi[mi], blo[ni]);
          MMA16816(acc[mi][ni], alo[mi], bhi[ni]);
        }
    }
    __syncthreads();
  }

#pragma unroll
  for (int mi = 0; mi < 4; mi++) {
    const int m0 = brow + warp_m + mi * 16 + g;
    const int m1 = m0 + 8;
#pragma unroll
    for (int ni = 0; ni < 4; ni++) {
      const int n = bcol + warp_n + ni * 8 + tg * 2;
      const float bx = bias[n], by = bias[n + 1];
      const float v0 = acc[mi][ni][0] + bx, v1 = acc[mi][ni][1] + by;
      const float v2 = acc[mi][ni][2] + bx, v3 = acc[mi][ni][3] + by;
      if (MODE == 0) {
        *(float2*)(Cf + (size_t)m0 * DM + n) = make_float2(v0, v1);
        *(float2*)(Cf + (size_t)m1 * DM + n) = make_float2(v2, v3);
      } else if (MODE == 1) {
        uint32_t h, l;
        const int i0 = ((m0 >> 11) * NH + (n >> 6)) * (SEQ * DEPTH) +
                       (m0 & (SEQ - 1)) * DEPTH + (n & (DEPTH - 1));
        split_pack2(v0, v1, h, l);
        *(uint32_t*)(Chi + i0) = h;
        *(uint32_t*)(Clo + i0) = l;
        const int i1 = ((m1 >> 11) * NH + (n >> 6)) * (SEQ * DEPTH) +
                       (m1 & (SEQ - 1)) * DEPTH + (n & (DEPTH - 1));
        split_pack2(v2, v3, h, l);
        *(uint32_t*)(Chi + i1) = h;
        *(uint32_t*)(Clo + i1) = l;
      } else {
        // transposed head-split: idx = ((b*NH+h)*DEPTH + d)*SEQ + s
        const int h = n >> 6, d0 = n & 63;
        const float vals[4] = {v0, v1, v2, v3};
        const int ms[2] = {m0, m1};
#pragma unroll
        for (int rr = 0; rr < 2; rr++) {
          const int bb = ms[rr] >> 11, s = ms[rr] & (SEQ - 1);
#pragma unroll
          for (int e = 0; e < 2; e++) {
            const float val = vals[rr * 2 + e];
            const size_t idx =
                ((size_t)(bb * NH + h) * DEPTH + d0 + e) * SEQ + s;
            bf16 hv = __float2bfloat16_rn(val);
            Chi[idx] = hv;
            Clo[idx] = __float2bfloat16_rn(val - __bfloat162float(hv));
          }
        }
      }
    }
  }
}

// ---------------------------------------------------------------------------
// Tensor-core causal flash attention (bf16x3 for QK^T and PV).
// Block: 1 (b,h) x 64 Q rows, 4 warps (16 rows each). K-tile 64.
// smem per stage: Khi,Klo [key][d], Vthi,Vtlo [d][key], 144B row stride.
// ---------------------------------------------------------------------------
#define FSTRIDE 144
#define FTILE_B (64 * FSTRIDE)     // 9216
#define FSTAGE_B (4 * FTILE_B)     // 36864
#define FLASH_SMEM (2 * FSTAGE_B)  // 73728

__global__ __launch_bounds__(128) void flash_mma(
    const bf16* __restrict__ Qhi, const bf16* __restrict__ Qlo,
    const bf16* __restrict__ Khi, const bf16* __restrict__ Klo,
    const bf16* __restrict__ Vthi, const bf16* __restrict__ Vtlo,
    bf16* __restrict__ Ohi, bf16* __restrict__ Olo) {
  extern __shared__ char sm[];
  const int tid = threadIdx.x;
  const int warp = tid >> 5, lane = tid & 31;
  const int g = lane >> 2, tg = lane & 3;
  const int qt = blockIdx.x, bh = blockIdx.y;

  const bf16* kb_hi = Khi + (size_t)bh * SEQ * DEPTH;
  const bf16* kb_lo = Klo + (size_t)bh * SEQ * DEPTH;
  const bf16* vb_hi = Vthi + (size_t)bh * DEPTH * SEQ;
  const bf16* vb_lo = Vtlo + (size_t)bh * DEPTH * SEQ;

  auto load_kv = [&](int kt, int st) {
    char* base = sm + st * FSTAGE_B;
    const bf16* khs = kb_hi + kt * 64 * DEPTH;
    const bf16* kls = kb_lo + kt * 64 * DEPTH;
#pragma unroll
    for (int i = tid; i < 512; i += 128) {
      const int r = i >> 3, c = i & 7;
      const uint32_t d0 = smem_u32(base + r * FSTRIDE + c * 16);
      cp_async16(d0, khs + r * DEPTH + c * 8);
      cp_async16(d0 + FTILE_B, kls + r * DEPTH + c * 8);
    }
    const bf16* vhs = vb_hi + kt * 64;
    const bf16* vls = vb_lo + kt * 64;
#pragma unroll
    for (int i = tid; i < 512; i += 128) {
      const int r = i >> 3, c = i & 7;
      const uint32_t d0 = smem_u32(base + 2 * FTILE_B + r * FSTRIDE + c * 16);
      cp_async16(d0, vhs + (size_t)r * SEQ + c * 8);
      cp_async16(d0 + FTILE_B, vls + (size_t)r * SEQ + c * 8);
    }
    CP_COMMIT();
  };

  // Q fragments (held for the whole block)
  uint32_t qfh[4][4], qfl[4][4];
  {
    const bf16* qb_hi = Qhi + (size_t)(bh * SEQ + qt * 64 + warp * 16) * DEPTH;
    const bf16* qb_lo = Qlo + (size_t)(bh * SEQ + qt * 64 + warp * 16) * DEPTH;
#pragma unroll
    for (int kb = 0; kb < 4; kb++) {
      const int c0 = kb * 16 + tg * 2;
      qfh[kb][0] = *(const uint32_t*)(qb_hi + g * DEPTH + c0);
      qfh[kb][1] = *(const uint32_t*)(qb_hi + (g + 8) * DEPTH + c0);
      qfh[kb][2] = *(const uint32_t*)(qb_hi + g * DEPTH + c0 + 8);
      qfh[kb][3] = *(const uint32_t*)(qb_hi + (g + 8) * DEPTH + c0 + 8);
      qfl[kb][0] = *(const uint32_t*)(qb_lo + g * DEPTH + c0);
      qfl[kb][1] = *(const uint32_t*)(qb_lo + (g + 8) * DEPTH + c0);
      qfl[kb][2] = *(const uint32_t*)(qb_lo + g * DEPTH + c0 + 8);
      qfl[kb][3] = *(const uint32_t*)(qb_lo + (g + 8) * DEPTH + c0 + 8);
    }
  }

  float o[8][4];
#pragma unroll
  for (int nb = 0; nb < 8; nb++)
#pragma unroll
    for (int r = 0; r < 4; r++) o[nb][r] = 0.f;
  float m0 = -1e30f, m1 = -1e30f, l0 = 0.f, l1 = 0.f;

  load_kv(0, 0);

  for (int kt = 0; kt <= qt; kt++) {
    if (kt < qt) {
      load_kv(kt + 1, (kt + 1) & 1);
      CP_WAIT(1);
    } else {
      CP_WAIT(0);
    }
    __syncthreads();
    const char* base = sm + (kt & 1) * FSTAGE_B;

    // S = Q K^T (bf16x3)
    float sacc[8][4];
#pragma unroll
    for (int nb = 0; nb < 8; nb++)
#pragma unroll
      for (int r = 0; r < 4; r++) sacc[nb][r] = 0.f;
#pragma unroll
    for (int nb = 0; nb < 8; nb++) {
      const char* krow = base + (nb * 8 + g) * FSTRIDE;
#pragma unroll
      for (int kb = 0; kb < 4; kb++) {
        const int off = kb * 32 + tg * 4;
        uint32_t Bh[2], Bl[2];
        Bh[0] = *(const uint32_t*)(krow + off);
        Bh[1] = *(const uint32_t*)(krow + off + 16);
        Bl[0] = *(const uint32_t*)(krow + FTILE_B + off);
        Bl[1] = *(const uint32_t*)(krow + FTILE_B + off + 16);
        MMA16816(sacc[nb], qfh[kb], Bh);
        MMA16816(sacc[nb], qfh[kb], Bl);
        MMA16816(sacc[nb], qfl[kb], Bh);
      }
    }

    // scale + causal mask
    const float scale = 0.125f;
#pragma unroll
    for (int nb = 0; nb < 8; nb++)
#pragma unroll
      for (int r = 0; r < 4; r++) sacc[nb][r] *= scale;
    if (kt == qt) {
      const int r0g = warp * 16 + g, r1g = r0g + 8;
#pragma unroll
      for (int nb = 0; nb < 8; nb++) {
        const int c = nb * 8 + tg * 2;
        if (c > r0g) sacc[nb][0] = -1e9f;
        if (c + 1 > r0g) sacc[nb][1] = -1e9f;
        if (c > r1g) sacc[nb][2] = -1e9f;
        if (c + 1 > r1g) sacc[nb][3] = -1e9f;
      }
    }

    // online softmax (rows g and g+8)
    float mx0 = -1e30f, mx1 = -1e30f;
#pragma unroll
    for (int nb = 0; nb < 8; nb++) {
      mx0 = fmaxf(mx0, fmaxf(sacc[nb][0], sacc[nb][1]));
      mx1 = fmaxf(mx1, fmaxf(sacc[nb][2], sacc[nb][3]));
    }
    mx0 = fmaxf(mx0, __shfl_xor_sync(0xffffffffu, mx0, 1));
    mx0 = fmaxf(mx0, __shfl_xor_sync(0xffffffffu, mx0, 2));
    mx1 = fmaxf(mx1, __shfl_xor_sync(0xffffffffu, mx1, 1));
    mx1 = fmaxf(mx1, __shfl_xor_sync(0xffffffffu, mx1, 2));
    const float mn0 = fmaxf(m0, mx0), mn1 = fmaxf(m1, mx1);
    const float al0 = __expf(m0 - mn0), al1 = __expf(m1 - mn1);
    m0 = mn0;
    m1 = mn1;
    float rs0 = 0.f, rs1 = 0.f;
#pragma unroll
    for (int nb = 0; nb < 8; nb++) {
      sacc[nb][0] = __expf(sacc[nb][0] - mn0);
      sacc[nb][1] = __expf(sacc[nb][1] - mn0);
      sacc[nb][2] = __expf(sacc[nb][2] - mn1);
      sacc[nb][3] = __expf(sacc[nb][3] - mn1);
      rs0 += sacc[nb][0] + sacc[nb][1];
      rs1 += sacc[nb][2] + sacc[nb][3];
    }
    rs0 += __shfl_xor_sync(0xffffffffu, rs0, 1);
    rs0 += __shfl_xor_sync(0xffffffffu, rs0, 2);
    rs1 += __shfl_xor_sync(0xffffffffu, rs1, 1);
    rs1 += __shfl_xor_sync(0xffffffffu, rs1, 2);
    l0 = l0 * al0 + rs0;
    l1 = l1 * al1 + rs1;
#pragma unroll
    for (int nb = 0; nb < 8; nb++) {
      o[nb][0] *= al0;
      o[nb][1] *= al0;
      o[nb][2] *= al1;
      o[nb][3] *= al1;
    }

    // P fragments (hi/lo) straight from S accumulators
    uint32_t pfh[4][4], pfl[4][4];
#pragma unroll
    for (int j = 0; j < 4; j++) {
      split_pack2(sacc[2 * j][0], sacc[2 * j][1], pfh[j][0], pfl[j][0]);
      split_pack2(sacc[2 * j][2], sacc[2 * j][3], pfh[j][1], pfl[j][1]);
      split_pack2(sacc[2 * j + 1][0], sacc[2 * j + 1][1], pfh[j][2], pfl[j][2]);
      split_pack2(sacc[2 * j + 1][2], sacc[2 * j + 1][3], pfh[j][3], pfl[j][3]);
    }

    // O += P V (bf16x3)
#pragma unroll
    for (int nb = 0; nb < 8; nb++) {
      const char* vrow = base + 2 * FTILE_B + (nb * 8 + g) * FSTRIDE;
#pragma unroll
      for (int j = 0; j < 4; j++) {
        const int off = j * 32 + tg * 4;
        uint32_t Vh[2], Vl[2];
        Vh[0] = *(const uint32_t*)(vrow + off);
        Vh[1] = *(const uint32_t*)(vrow + off + 16);
        Vl[0] = *(const uint32_t*)(vrow + FTILE_B + off);
        Vl[1] = *(const uint32_t*)(vrow + FTILE_B + off + 16);
        MMA16816(o[nb], pfh[j], Vh);
        MMA16816(o[nb], pfh[j], Vl);
        MMA16816(o[nb], pfl[j], Vh);
      }
    }
    __syncthreads();
  }

  // epilogue -> row-major (m, DM) bf16 hi/lo for the dense GEMM
  const float inv0 = 1.0f / l0, inv1 = 1.0f / l1;
  const int bb = bh >> 4, hh = bh & 15;
  const int s0 = qt * 64 + warp * 16 + g;
  const size_t row0 = ((size_t)bb * SEQ + s0) * DM + hh * 64;
  const size_t row1 = row0 + (size_t)8 * DM;
#pragma unroll
  for (int nb = 0; nb < 8; nb++) {
    const int col = nb * 8 + tg * 2;
    uint32_t h, l;
    split_pack2(o[nb][0] * inv0, o[nb][1] * inv0, h, l);
    *(uint32_t*)(Ohi + row0 + col) = h;
    *(uint32_t*)(Olo + row0 + col) = l;
    split_pack2(o[nb][2] * inv1, o[nb][3] * inv1, h, l);
    *(uint32_t*)(Ohi + row1 + col) = h;
    *(uint32_t*)(Olo + row1 + col) = l;
  }
}

// ---------------------------------------------------------------------------
extern "C" void kernel_launch(void* const* d_in, const int* in_sizes, int n_in,
                              void* d_out, int out_size) {
  const float* q = (const float*)d_in[0];
  const float* k = (const float*)d_in[1];
  const float* v = (const float*)d_in[2];
  const float* wq_w = (const float*)d_in[3];
  const float* wq_b = (const float*)d_in[4];
  const float* wk_w = (const float*)d_in[5];
  const float* wk_b = (const float*)d_in[6];
  const float* wv_w = (const float*)d_in[7];
  const float* wv_b = (const float*)d_in[8];
  const float* dense_w = (const float*)d_in[9];
  const float* dense_b = (const float*)d_in[10];
  float* out = (float*)d_out;

  bf16 *ihi, *ilo, *whi, *wlo, *qhi, *qlo, *khi, *klo, *vthi, *vtlo, *ohi, *olo;
  cudaGetSymbolAddress((void**)&ihi, g_ihi);
  cudaGetSymbolAddress((void**)&ilo, g_ilo);
  cudaGetSymbolAddress((void**)&whi, g_whi);
  cudaGetSymbolAddress((void**)&wlo, g_wlo);
  cudaGetSymbolAddress((void**)&qhi, g_qhi);
  cudaGetSymbolAddress((void**)&qlo, g_qlo);
  cudaGetSymbolAddress((void**)&khi, g_khi);
  cudaGetSymbolAddress((void**)&klo, g_klo);
  cudaGetSymbolAddress((void**)&vthi, g_vthi);
  cudaGetSymbolAddress((void**)&vtlo, g_vtlo);
  cudaGetSymbolAddress((void**)&ohi, g_ohi);
  cudaGetSymbolAddress((void**)&olo, g_olo);

  cudaFuncSetAttribute(gemm_mma<0>, cudaFuncAttributeMaxDynamicSharedMemorySize,
                       GEMM_SMEM);
  cudaFuncSetAttribute(gemm_mma<1>, cudaFuncAttributeMaxDynamicSharedMemorySize,
                       GEMM_SMEM);
  cudaFuncSetAttribute(gemm_mma<2>, cudaFuncAttributeMaxDynamicSharedMemorySize,
                       GEMM_SMEM);
  cudaFuncSetAttribute(flash_mma, cudaFuncAttributeMaxDynamicSharedMemorySize,
                       FLASH_SMEM);

  const size_t ISZ = (size_t)MROWS * DM;
  const size_t WSZ = (size_t)DM * DM;
  const int n4_in = MROWS * DM / 4;
  const int n4_w = DM * DM / 4;
  dim3 gg(DM / 128, MROWS / 128);  // (8, 64)

  split_rm<<<n4_in / 256, 256>>>(q, ihi + 0 * ISZ, ilo + 0 * ISZ, n4_in);
  split_rm<<<n4_in / 256, 256>>>(k, ihi + 1 * ISZ, ilo + 1 * ISZ, n4_in);
  split_rm<<<n4_in / 256, 256>>>(v, ihi + 2 * ISZ, ilo + 2 * ISZ, n4_in);
  split_rm<<<n4_w / 256, 256>>>(wq_w, whi + 0 * WSZ, wlo + 0 * WSZ, n4_w);
  split_rm<<<n4_w / 256, 256>>>(wk_w, whi + 1 * WSZ, wlo + 1 * WSZ, n4_w);
  split_rm<<<n4_w / 256, 256>>>(wv_w, whi + 2 * WSZ, wlo + 2 * WSZ, n4_w);
  split_rm<<<n4_w / 256, 256>>>(dense_w, whi + 3 * WSZ, wlo + 3 * WSZ, n4_w);

  gemm_mma<1><<<gg, 256, GEMM_SMEM>>>(ihi + 0 * ISZ, ilo + 0 * ISZ,
                                      whi + 0 * WSZ, wlo + 0 * WSZ, wq_b,
                                      nullptr, qhi, qlo);
  gemm_mma<1><<<gg, 256, GEMM_SMEM>>>(ihi + 1 * ISZ, ilo + 1 * ISZ,
                                      whi + 1 * WSZ, wlo + 1 * WSZ, wk_b,
                                      nullptr, khi, klo);
  gemm_mma<2><<<gg, 256, GEMM_SMEM>>>(ihi + 2 * ISZ, ilo + 2 * ISZ,
                                      whi + 2 * WSZ, wlo + 2 * WSZ, wv_b,
                                      nullptr, vthi, vtlo);

  dim3 fg(SEQ / 64, BATCH * NH);  // (32, 64)
  flash_mma<<<fg, 128, FLASH_SMEM>>>(qhi, qlo, khi, klo, vthi, vtlo, ohi, olo);

  gemm_mma<0><<<gg, 256, GEMM_SMEM>>>(ohi, olo, whi + 3 * WSZ, wlo + 3 * WSZ,
                                      dense_b, out, nullptr, nullptr);
}